// round 6
// baseline (speedup 1.0000x reference)
#include <cuda_runtime.h>

// Scratch (device globals — no runtime allocation allowed)
__device__ float g_part   [4 * 64 * 1024];  // partial column sums of v (64 chunks of 16 rows)
__device__ float g_rowpart[8 * 4 * 1024];   // split-K partials of vsum @ Wv
__device__ float g_wosum  [64 * 1024];      // WoSum[d][m] = sum_j Wo[j*64+d][m]
__device__ float g_outrows[64 * 1024];      // 16 distinct out rows per batch

// ---------------------------------------------------------------------------
// L1 (fused): blocks 0..255 -> colsum of v; blocks 256..319 -> wosum of Wo.
// ---------------------------------------------------------------------------
__global__ __launch_bounds__(256) void prep_kernel(const float* __restrict__ v,
                                                   const float* __restrict__ Wo,
                                                   float* __restrict__ part,
                                                   float* __restrict__ wosum) {
    const int t = threadIdx.x;
    if (blockIdx.x < 256) {
        const int s = blockIdx.x >> 2, b = blockIdx.x & 3;
        const float4* p = (const float4*)(v + ((size_t)(b * 1024 + s * 16)) * 1024) + t;
        float4 a0 = make_float4(0.f, 0.f, 0.f, 0.f);
        float4 a1 = make_float4(0.f, 0.f, 0.f, 0.f);
#pragma unroll
        for (int i = 0; i < 16; i += 2) {
            float4 x = p[(size_t)i * 256];
            float4 y = p[(size_t)(i + 1) * 256];
            a0.x += x.x; a0.y += x.y; a0.z += x.z; a0.w += x.w;
            a1.x += y.x; a1.y += y.y; a1.z += y.z; a1.w += y.w;
        }
        float4 r = make_float4(a0.x + a1.x, a0.y + a1.y, a0.z + a1.z, a0.w + a1.w);
        ((float4*)(part + (size_t)(b * 64 + s) * 1024))[t] = r;
    } else {
        const int d = blockIdx.x - 256;      // 0..63
        const float4* src = (const float4*)(Wo + (size_t)d * 1024) + t;
        float4 a0 = make_float4(0.f, 0.f, 0.f, 0.f);
        float4 a1 = make_float4(0.f, 0.f, 0.f, 0.f);
        float4 a2 = make_float4(0.f, 0.f, 0.f, 0.f);
        float4 a3 = make_float4(0.f, 0.f, 0.f, 0.f);
#pragma unroll
        for (int j = 0; j < 16; j += 4) {
            float4 x0 = src[(size_t)(j + 0) * 64 * 256];
            float4 x1 = src[(size_t)(j + 1) * 64 * 256];
            float4 x2 = src[(size_t)(j + 2) * 64 * 256];
            float4 x3 = src[(size_t)(j + 3) * 64 * 256];
            a0.x += x0.x; a0.y += x0.y; a0.z += x0.z; a0.w += x0.w;
            a1.x += x1.x; a1.y += x1.y; a1.z += x1.z; a1.w += x1.w;
            a2.x += x2.x; a2.y += x2.y; a2.z += x2.z; a2.w += x2.w;
            a3.x += x3.x; a3.y += x3.y; a3.z += x3.z; a3.w += x3.w;
        }
        float4 r = make_float4(a0.x + a1.x + a2.x + a3.x,
                               a0.y + a1.y + a2.y + a3.y,
                               a0.z + a1.z + a2.z + a3.z,
                               a0.w + a1.w + a2.w + a3.w);
        ((float4*)(wosum + (size_t)d * 1024))[t] = r;
    }
}

// ---------------------------------------------------------------------------
// L2: split-K of rowsum[b][o] = sum_k vsum[b][k] * Wv[k][o].
// ---------------------------------------------------------------------------
__global__ __launch_bounds__(256) void vwv_kernel(const float* __restrict__ part,
                                                  const float* __restrict__ Wv,
                                                  float* __restrict__ rowpart) {
    __shared__ float vs[4][128];
    const int oc = blockIdx.x, kc = blockIdx.y, t = threadIdx.x;
    for (int idx = t; idx < 512; idx += 256) {
        int b = idx >> 7, kk = idx & 127;
        int k = kc * 128 + kk;
        float a0 = 0.f, a1 = 0.f;
#pragma unroll
        for (int s = 0; s < 64; s += 2) {
            a0 += part[(size_t)(b * 64 + s) * 1024 + k];
            a1 += part[(size_t)(b * 64 + s + 1) * 1024 + k];
        }
        vs[b][kk] = a0 + a1;
    }
    __syncthreads();
    const int o = oc * 256 + t;
    float a0 = 0.f, a1 = 0.f, a2 = 0.f, a3 = 0.f;
#pragma unroll 8
    for (int kk = 0; kk < 128; ++kk) {
        float w = Wv[(size_t)(kc * 128 + kk) * 1024 + o];
        a0 = fmaf(vs[0][kk], w, a0);
        a1 = fmaf(vs[1][kk], w, a1);
        a2 = fmaf(vs[2][kk], w, a2);
        a3 = fmaf(vs[3][kk], w, a3);
    }
    float* rp = rowpart + (size_t)kc * 4096;
    rp[0 * 1024 + o] = a0;
    rp[1 * 1024 + o] = a1;
    rp[2 * 1024 + o] = a2;
    rp[3 * 1024 + o] = a3;
}

// ---------------------------------------------------------------------------
// L3: outrows = rs @ wosum   ([64,64] @ [64,1024]) with smem staging.
// ---------------------------------------------------------------------------
__global__ __launch_bounds__(256) void outrows_kernel(const float* __restrict__ rowpart,
                                                      const float* __restrict__ wosum,
                                                      float* __restrict__ outrows) {
    __shared__ float4 ws[64][32];   // [d][m4] : 64 x 128 floats = 32 KB
    __shared__ float  rs[8][64];
    const int mc = blockIdx.x, bng = blockIdx.y, t = threadIdx.x;

#pragma unroll
    for (int it = 0; it < 8; ++it) {
        int idx = t + it * 256;            // 0..2047
        int d = idx >> 5, m4 = idx & 31;
        ws[d][m4] = *((const float4*)(wosum + (size_t)d * 1024 + mc * 128) + m4);
    }
#pragma unroll
    for (int it = 0; it < 2; ++it) {
        int idx = t + it * 256;            // 0..511
        int bnl = idx >> 6, d = idx & 63;
        int bn = bng * 8 + bnl;
        int b = bn >> 4, o = (bn & 15) * 64 + d;
        float a = 0.f;
#pragma unroll
        for (int kc = 0; kc < 8; ++kc)
            a += rowpart[(size_t)(kc * 4 + b) * 1024 + o];
        rs[bnl][d] = a;
    }
    __syncthreads();

    const int bnl = t >> 5, m4 = t & 31;   // warp = bnl -> rs broadcast
    float4 acc = make_float4(0.f, 0.f, 0.f, 0.f);
#pragma unroll
    for (int d = 0; d < 64; ++d) {
        float a = rs[bnl][d];
        float4 w = ws[d][m4];
        acc.x = fmaf(a, w.x, acc.x);
        acc.y = fmaf(a, w.y, acc.y);
        acc.z = fmaf(a, w.z, acc.z);
        acc.w = fmaf(a, w.w, acc.w);
    }
    const int bn = bng * 8 + bnl;
    *((float4*)(outrows + (size_t)bn * 1024 + mc * 128) + m4) = acc;
}

// ---------------------------------------------------------------------------
// L4: residual add + LayerNorm, TWO WARPS PER ROW (occupancy fix).
// Block = 256 thr = 8 warps = 4 rows. Each warp owns a 512-float half-row
// (4 float4/thread). 8192 warps total -> ~55 warps/SM in flight.
// ---------------------------------------------------------------------------
__global__ __launch_bounds__(256) void ln_kernel(const float* __restrict__ outrows,
                                                 const float* __restrict__ q,
                                                 const float* __restrict__ gamma,
                                                 const float* __restrict__ beta,
                                                 float* __restrict__ out) {
    __shared__ float2 psum[8];
    const int warp = threadIdx.x >> 5, lane = threadIdx.x & 31;
    const int rloc = warp >> 1, half = warp & 1;
    const int row  = blockIdx.x * 4 + rloc;            // 0..4095
    const int bn   = (row >> 10) * 16 + ((row & 1023) >> 6);
    const int f4   = half * 128 + lane;                // float4 index base

    const float4* yp = (const float4*)(outrows + (size_t)bn * 1024) + f4;
    const float4* rp = (const float4*)(q + (size_t)row * 1024) + f4;

    float4 x[4];
    float s = 0.f, sq = 0.f;
#pragma unroll
    for (int it = 0; it < 4; ++it) {
        float4 y = yp[it * 32];
        float4 r = rp[it * 32];
        float4 xv = make_float4(y.x + r.x, y.y + r.y, y.z + r.z, y.w + r.w);
        x[it] = xv;
        s  += xv.x + xv.y + xv.z + xv.w;
        sq += xv.x * xv.x + xv.y * xv.y + xv.z * xv.z + xv.w * xv.w;
    }
#pragma unroll
    for (int off = 16; off >= 1; off >>= 1) {
        s  += __shfl_xor_sync(0xffffffffu, s,  off);
        sq += __shfl_xor_sync(0xffffffffu, sq, off);
    }
    if (lane == 0) psum[warp] = make_float2(s, sq);
    __syncthreads();
    {
        float2 a = psum[rloc * 2], b = psum[rloc * 2 + 1];
        s = a.x + b.x; sq = a.y + b.y;
    }
    const float mean = s * (1.f / 1024.f);
    const float inv  = rsqrtf(sq * (1.f / 1024.f) - mean * mean + 1e-6f);

    const float4* gp = (const float4*)gamma + f4;
    const float4* bp = (const float4*)beta  + f4;
    float4* op = (float4*)(out + (size_t)row * 1024) + f4;
#pragma unroll
    for (int it = 0; it < 4; ++it) {
        float4 g  = gp[it * 32];
        float4 bt = bp[it * 32];
        float4 xv = x[it];
        op[it * 32] = make_float4((xv.x - mean) * inv * g.x + bt.x,
                                  (xv.y - mean) * inv * g.y + bt.y,
                                  (xv.z - mean) * inv * g.z + bt.z,
                                  (xv.w - mean) * inv * g.w + bt.w);
    }
}

// ---------------------------------------------------------------------------
extern "C" void kernel_launch(void* const* d_in, const int* in_sizes, int n_in,
                              void* d_out, int out_size) {
    (void)in_sizes; (void)n_in; (void)out_size;
    const float* q     = (const float*)d_in[0];
    const float* v     = (const float*)d_in[2];
    const float* Wv    = (const float*)d_in[6];
    const float* Wo    = (const float*)d_in[7];
    const float* gamma = (const float*)d_in[8];
    const float* beta  = (const float*)d_in[9];
    float* out = (float*)d_out;

    float *part, *rowpart, *wosum, *outrows;
    cudaGetSymbolAddress((void**)&part,    g_part);
    cudaGetSymbolAddress((void**)&rowpart, g_rowpart);
    cudaGetSymbolAddress((void**)&wosum,   g_wosum);
    cudaGetSymbolAddress((void**)&outrows, g_outrows);

    prep_kernel   <<<320, 256>>>(v, Wo, part, wosum);
    vwv_kernel    <<<dim3(4, 8), 256>>>(part, Wv, rowpart);
    outrows_kernel<<<dim3(8, 8), 256>>>(rowpart, wosum, outrows);
    ln_kernel     <<<1024, 256>>>(outrows, q, gamma, beta, out);
}

// round 7
// speedup vs baseline: 1.1001x; 1.1001x over previous
#include <cuda_runtime.h>

// Scratch (device globals — no runtime allocation allowed)
__device__ float g_part   [4 * 64 * 1024];  // partial column sums of v (64 chunks of 16 rows)
__device__ float g_rowpart[8 * 4 * 1024];   // split-K partials of vsum @ Wv
__device__ float g_wosum  [64 * 1024];      // WoSum[d][m] = sum_j Wo[j*64+d][m]
__device__ float g_outrows[64 * 1024];      // 16 distinct out rows per batch
__device__ unsigned int g_flag;             // producer-done counter (reset by prep)

// ---------------------------------------------------------------------------
// L1 (fused): blocks 0..255 -> colsum of v; blocks 256..319 -> wosum of Wo.
// Block 256 thread 0 also resets the spin flag for this replay.
// ---------------------------------------------------------------------------
__global__ __launch_bounds__(256) void prep_kernel(const float* __restrict__ v,
                                                   const float* __restrict__ Wo,
                                                   float* __restrict__ part,
                                                   float* __restrict__ wosum) {
    const int t = threadIdx.x;
    if (blockIdx.x < 256) {
        const int s = blockIdx.x >> 2, b = blockIdx.x & 3;
        const float4* p = (const float4*)(v + ((size_t)(b * 1024 + s * 16)) * 1024) + t;
        float4 a0 = make_float4(0.f, 0.f, 0.f, 0.f);
        float4 a1 = make_float4(0.f, 0.f, 0.f, 0.f);
#pragma unroll
        for (int i = 0; i < 16; i += 2) {
            float4 x = p[(size_t)i * 256];
            float4 y = p[(size_t)(i + 1) * 256];
            a0.x += x.x; a0.y += x.y; a0.z += x.z; a0.w += x.w;
            a1.x += y.x; a1.y += y.y; a1.z += y.z; a1.w += y.w;
        }
        float4 r = make_float4(a0.x + a1.x, a0.y + a1.y, a0.z + a1.z, a0.w + a1.w);
        ((float4*)(part + (size_t)(b * 64 + s) * 1024))[t] = r;
    } else {
        if (blockIdx.x == 256 && t == 0) g_flag = 0u;   // reset for this replay
        const int d = blockIdx.x - 256;      // 0..63
        const float4* src = (const float4*)(Wo + (size_t)d * 1024) + t;
        float4 a0 = make_float4(0.f, 0.f, 0.f, 0.f);
        float4 a1 = make_float4(0.f, 0.f, 0.f, 0.f);
        float4 a2 = make_float4(0.f, 0.f, 0.f, 0.f);
        float4 a3 = make_float4(0.f, 0.f, 0.f, 0.f);
#pragma unroll
        for (int j = 0; j < 16; j += 4) {
            float4 x0 = src[(size_t)(j + 0) * 64 * 256];
            float4 x1 = src[(size_t)(j + 1) * 64 * 256];
            float4 x2 = src[(size_t)(j + 2) * 64 * 256];
            float4 x3 = src[(size_t)(j + 3) * 64 * 256];
            a0.x += x0.x; a0.y += x0.y; a0.z += x0.z; a0.w += x0.w;
            a1.x += x1.x; a1.y += x1.y; a1.z += x1.z; a1.w += x1.w;
            a2.x += x2.x; a2.y += x2.y; a2.z += x2.z; a2.w += x2.w;
            a3.x += x3.x; a3.y += x3.y; a3.z += x3.z; a3.w += x3.w;
        }
        float4 r = make_float4(a0.x + a1.x + a2.x + a3.x,
                               a0.y + a1.y + a2.y + a3.y,
                               a0.z + a1.z + a2.z + a3.z,
                               a0.w + a1.w + a2.w + a3.w);
        ((float4*)(wosum + (size_t)d * 1024))[t] = r;
    }
}

// ---------------------------------------------------------------------------
// L2 (fused vwv + outrows via spin barrier; 96 blocks, all wave-1 resident)
// Blocks 0..31  (producers): rowpart[kc][b][o] partial GEMM, fence, count++.
// Blocks 32..95 (consumers): stage wosum tile (overlaps producers), spin until
// count==32, fold split-K rowpart -> rs, tiny GEMM -> outrows.
// ---------------------------------------------------------------------------
__global__ __launch_bounds__(256) void mid_kernel(const float* __restrict__ part,
                                                  const float* __restrict__ Wv,
                                                  const float* __restrict__ wosum,
                                                  float* __restrict__ rowpart,
                                                  float* __restrict__ outrows) {
    __shared__ float smem_buf[64 * 128 + 8 * 64];   // 34 KB, unioned usage
    const int t = threadIdx.x;

    if (blockIdx.x < 32) {
        // ---- producer: vwv ----
        float* vs = smem_buf;                        // [4][128]
        const int oc = blockIdx.x & 3, kc = blockIdx.x >> 2;
        for (int idx = t; idx < 512; idx += 256) {
            int b = idx >> 7, kk = idx & 127;
            int k = kc * 128 + kk;
            float a0 = 0.f, a1 = 0.f;
#pragma unroll
            for (int s = 0; s < 64; s += 2) {
                a0 += part[(size_t)(b * 64 + s) * 1024 + k];
                a1 += part[(size_t)(b * 64 + s + 1) * 1024 + k];
            }
            vs[b * 128 + kk] = a0 + a1;
        }
        __syncthreads();
        const int o = oc * 256 + t;
        float a0 = 0.f, a1 = 0.f, a2 = 0.f, a3 = 0.f;
#pragma unroll 8
        for (int kk = 0; kk < 128; ++kk) {
            float w = Wv[(size_t)(kc * 128 + kk) * 1024 + o];
            a0 = fmaf(vs[0 * 128 + kk], w, a0);
            a1 = fmaf(vs[1 * 128 + kk], w, a1);
            a2 = fmaf(vs[2 * 128 + kk], w, a2);
            a3 = fmaf(vs[3 * 128 + kk], w, a3);
        }
        float* rp = rowpart + (size_t)kc * 4096;
        rp[0 * 1024 + o] = a0;
        rp[1 * 1024 + o] = a1;
        rp[2 * 1024 + o] = a2;
        rp[3 * 1024 + o] = a3;
        __threadfence();
        __syncthreads();
        if (t == 0) atomicAdd(&g_flag, 1u);
    } else {
        // ---- consumer: outrows ----
        float4* ws = (float4*)smem_buf;              // [64][32] float4
        float*  rs = smem_buf + 64 * 128;            // [8][64]
        const int r = blockIdx.x - 32;
        const int mc = r & 7, bng = r >> 3;

        // stage wosum tile while producers run
#pragma unroll
        for (int it = 0; it < 8; ++it) {
            int idx = t + it * 256;            // 0..2047
            int d = idx >> 5, m4 = idx & 31;
            ws[d * 32 + m4] = *((const float4*)(wosum + (size_t)d * 1024 + mc * 128) + m4);
        }

        // wait for all producers
        if (t == 0) {
            while (atomicAdd(&g_flag, 0u) < 32u) { }
        }
        __syncthreads();

#pragma unroll
        for (int it = 0; it < 2; ++it) {
            int idx = t + it * 256;            // 0..511
            int bnl = idx >> 6, d = idx & 63;
            int bn = bng * 8 + bnl;
            int b = bn >> 4, o = (bn & 15) * 64 + d;
            float a = 0.f;
#pragma unroll
            for (int kc = 0; kc < 8; ++kc)
                a += rowpart[(size_t)(kc * 4 + b) * 1024 + o];
            rs[bnl * 64 + d] = a;
        }
        __syncthreads();

        const int bnl = t >> 5, m4 = t & 31;   // warp = bnl -> rs broadcast
        float4 acc = make_float4(0.f, 0.f, 0.f, 0.f);
#pragma unroll
        for (int d = 0; d < 64; ++d) {
            float a = rs[bnl * 64 + d];
            float4 w = ws[d * 32 + m4];
            acc.x = fmaf(a, w.x, acc.x);
            acc.y = fmaf(a, w.y, acc.y);
            acc.z = fmaf(a, w.z, acc.z);
            acc.w = fmaf(a, w.w, acc.w);
        }
        const int bn = bng * 8 + bnl;
        *((float4*)(outrows + (size_t)bn * 1024 + mc * 128) + m4) = acc;
    }
}

// ---------------------------------------------------------------------------
// L3: residual add + LayerNorm, FOUR WARPS PER ROW.
// Block = 256 thr = 8 warps = 2 rows; grid 2048 -> 16384 warps total.
// Thread owns 2 float4 of q + 2 of outrows (quarter-row per warp).
// ---------------------------------------------------------------------------
__global__ __launch_bounds__(256) void ln_kernel(const float* __restrict__ outrows,
                                                 const float* __restrict__ q,
                                                 const float* __restrict__ gamma,
                                                 const float* __restrict__ beta,
                                                 float* __restrict__ out) {
    __shared__ float2 psum[8];
    const int warp = threadIdx.x >> 5, lane = threadIdx.x & 31;
    const int rloc = warp >> 2, qtr = warp & 3;
    const int row  = blockIdx.x * 2 + rloc;            // 0..4095
    const int bn   = (row >> 10) * 16 + ((row & 1023) >> 6);
    const int f4   = qtr * 64 + lane;                  // float4 index base

    const float4* yp = (const float4*)(outrows + (size_t)bn * 1024) + f4;
    const float4* rp = (const float4*)(q + (size_t)row * 1024) + f4;

    float4 y0 = yp[0], y1 = yp[32];
    float4 r0 = rp[0], r1 = rp[32];
    float4 x0 = make_float4(y0.x + r0.x, y0.y + r0.y, y0.z + r0.z, y0.w + r0.w);
    float4 x1 = make_float4(y1.x + r1.x, y1.y + r1.y, y1.z + r1.z, y1.w + r1.w);

    float s  = x0.x + x0.y + x0.z + x0.w + x1.x + x1.y + x1.z + x1.w;
    float sq = x0.x * x0.x + x0.y * x0.y + x0.z * x0.z + x0.w * x0.w
             + x1.x * x1.x + x1.y * x1.y + x1.z * x1.z + x1.w * x1.w;
#pragma unroll
    for (int off = 16; off >= 1; off >>= 1) {
        s  += __shfl_xor_sync(0xffffffffu, s,  off);
        sq += __shfl_xor_sync(0xffffffffu, sq, off);
    }
    if (lane == 0) psum[warp] = make_float2(s, sq);
    __syncthreads();
    {
        float2 a = psum[rloc * 4 + 0], b = psum[rloc * 4 + 1];
        float2 c = psum[rloc * 4 + 2], d = psum[rloc * 4 + 3];
        s  = a.x + b.x + c.x + d.x;
        sq = a.y + b.y + c.y + d.y;
    }
    const float mean = s * (1.f / 1024.f);
    const float inv  = rsqrtf(sq * (1.f / 1024.f) - mean * mean + 1e-6f);

    const float4* gp = (const float4*)gamma + f4;
    const float4* bp = (const float4*)beta  + f4;
    float4 g0 = gp[0], g1 = gp[32];
    float4 b0 = bp[0], b1 = bp[32];
    float4* op = (float4*)(out + (size_t)row * 1024) + f4;
    op[0]  = make_float4((x0.x - mean) * inv * g0.x + b0.x,
                         (x0.y - mean) * inv * g0.y + b0.y,
                         (x0.z - mean) * inv * g0.z + b0.z,
                         (x0.w - mean) * inv * g0.w + b0.w);
    op[32] = make_float4((x1.x - mean) * inv * g1.x + b1.x,
                         (x1.y - mean) * inv * g1.y + b1.y,
                         (x1.z - mean) * inv * g1.z + b1.z,
                         (x1.w - mean) * inv * g1.w + b1.w);
}

// ---------------------------------------------------------------------------
extern "C" void kernel_launch(void* const* d_in, const int* in_sizes, int n_in,
                              void* d_out, int out_size) {
    (void)in_sizes; (void)n_in; (void)out_size;
    const float* q     = (const float*)d_in[0];
    const float* v     = (const float*)d_in[2];
    const float* Wv    = (const float*)d_in[6];
    const float* Wo    = (const float*)d_in[7];
    const float* gamma = (const float*)d_in[8];
    const float* beta  = (const float*)d_in[9];
    float* out = (float*)d_out;

    float *part, *rowpart, *wosum, *outrows;
    cudaGetSymbolAddress((void**)&part,    g_part);
    cudaGetSymbolAddress((void**)&rowpart, g_rowpart);
    cudaGetSymbolAddress((void**)&wosum,   g_wosum);
    cudaGetSymbolAddress((void**)&outrows, g_outrows);

    prep_kernel<<<320, 256>>>(v, Wo, part, wosum);
    mid_kernel <<<96, 256>>>(part, Wv, wosum, rowpart, outrows);
    ln_kernel  <<<2048, 256>>>(outrows, q, gamma, beta, out);
}